// round 7
// baseline (speedup 1.0000x reference)
#include <cuda_runtime.h>

#define NN 50000
#define NE 600000
#define HD 128
#define NG 128
#define SCAN_B 1024
#define NSCANB ((NN + SCAN_B - 1) / SCAN_B)   // 49

// ---------------- scratch (static device globals; no allocations) ------------
__device__ float g_hA[NN * HD];     // current node features (relu'd layer output)
__device__ float g_hB[NN * HD];     // m * dinv[row]
__device__ float g_dinv[NN];
__device__ int   g_degi[NN];        // incoming edge count (no self loop)
__device__ int   g_scan[NN];
__device__ int   g_bsum[NSCANB];
__device__ int   g_boff[NSCANB];
__device__ int   g_rowstart[NN];
__device__ int   g_cursor[NN];
__device__ int   g_csrc[NE];        // CSR (by dest): source node ids

// ---------------- prep ------------------------------------------------------
__global__ void k_prep(float* __restrict__ out) {
    int i = blockIdx.x * blockDim.x + threadIdx.x;
    if (i < NN) g_degi[i] = 0;
    if (i < NG) out[i] = 0.0f;
}

__global__ void k_deg(const int* __restrict__ ei) {
    int e = blockIdx.x * blockDim.x + threadIdx.x;
    if (e < NE) atomicAdd(&g_degi[ei[NE + e]], 1);
}

__global__ void k_dinv() {
    int i = blockIdx.x * blockDim.x + threadIdx.x;
    if (i < NN) g_dinv[i] = rsqrtf((float)g_degi[i] + 1.0f);
}

// ---------------- scan (exclusive prefix over g_degi) -----------------------
__global__ __launch_bounds__(SCAN_B) void k_scan1() {
    __shared__ int sd[SCAN_B];
    int tid = threadIdx.x;
    int idx = blockIdx.x * SCAN_B + tid;
    int v = (idx < NN) ? g_degi[idx] : 0;
    sd[tid] = v;
    __syncthreads();
    for (int off = 1; off < SCAN_B; off <<= 1) {
        int t = (tid >= off) ? sd[tid - off] : 0;
        __syncthreads();
        sd[tid] += t;
        __syncthreads();
    }
    if (idx < NN) g_scan[idx] = sd[tid];
    if (tid == SCAN_B - 1) g_bsum[blockIdx.x] = sd[tid];
}

__global__ void k_scan2() {
    if (threadIdx.x == 0) {
        int a = 0;
        for (int b = 0; b < NSCANB; b++) { g_boff[b] = a; a += g_bsum[b]; }
    }
}

__global__ void k_scan3() {
    int i = blockIdx.x * blockDim.x + threadIdx.x;
    if (i < NN) {
        int rs = g_scan[i] - g_degi[i] + g_boff[i >> 10];
        g_rowstart[i] = rs;
        g_cursor[i] = rs;
    }
}

__global__ void k_fill(const int* __restrict__ ei) {
    int e = blockIdx.x * blockDim.x + threadIdx.x;
    if (e < NE) {
        int r = ei[e], c = ei[NE + e];
        int slot = atomicAdd(&g_cursor[c], 1);
        g_csrc[slot] = r;
    }
}

// ---------------- input MLP: g_hA = relu(x@W1 + b1) @ W2 + b2 ---------------
__global__ __launch_bounds__(256) void k_gemm_in(
    const float* __restrict__ x,
    const float* __restrict__ W1, const float* __restrict__ b1,
    const float* __restrict__ W2, const float* __restrict__ b2)
{
    __shared__ float sA[64][32];
    __shared__ float sB[32][HD];
    __shared__ float sx[64];
    __shared__ float sW1[32], sb1[32];

    int tid = threadIdx.x;
    int tx = tid & 31;
    int ty = tid >> 5;
    int nb = blockIdx.x * 64;

    if (tid < 64) { int gn = nb + tid; sx[tid] = (gn < NN) ? x[gn] : 0.0f; }

    float acc[8][4];
#pragma unroll
    for (int i = 0; i < 8; i++)
#pragma unroll
        for (int c = 0; c < 4; c++) acc[i][c] = 0.0f;

    for (int kc = 0; kc < 4; kc++) {
        __syncthreads();
        if (tid < 32) { sW1[tid] = W1[kc * 32 + tid]; sb1[tid] = b1[kc * 32 + tid]; }
        const float4* B4 = (const float4*)(W2 + kc * 32 * HD);
#pragma unroll
        for (int i = 0; i < 4; i++) ((float4*)sB)[tid + i * 256] = B4[tid + i * 256];
        __syncthreads();
#pragma unroll
        for (int i = 0; i < 8; i++) {
            int idx = tid + i * 256;
            int r = idx >> 5, k = idx & 31;
            sA[r][k] = fmaxf(fmaf(sx[r], sW1[k], sb1[k]), 0.0f);
        }
        __syncthreads();
#pragma unroll
        for (int kk = 0; kk < 32; kk += 4) {
            float4 bb0 = *(const float4*)&sB[kk + 0][tx * 4];
            float4 bb1 = *(const float4*)&sB[kk + 1][tx * 4];
            float4 bb2 = *(const float4*)&sB[kk + 2][tx * 4];
            float4 bb3 = *(const float4*)&sB[kk + 3][tx * 4];
#pragma unroll
            for (int i = 0; i < 8; i++) {
                float4 a = *(const float4*)&sA[ty * 8 + i][kk];
                acc[i][0] = fmaf(a.x, bb0.x, acc[i][0]); acc[i][1] = fmaf(a.x, bb0.y, acc[i][1]);
                acc[i][2] = fmaf(a.x, bb0.z, acc[i][2]); acc[i][3] = fmaf(a.x, bb0.w, acc[i][3]);
                acc[i][0] = fmaf(a.y, bb1.x, acc[i][0]); acc[i][1] = fmaf(a.y, bb1.y, acc[i][1]);
                acc[i][2] = fmaf(a.y, bb1.z, acc[i][2]); acc[i][3] = fmaf(a.y, bb1.w, acc[i][3]);
                acc[i][0] = fmaf(a.z, bb2.x, acc[i][0]); acc[i][1] = fmaf(a.z, bb2.y, acc[i][1]);
                acc[i][2] = fmaf(a.z, bb2.z, acc[i][2]); acc[i][3] = fmaf(a.z, bb2.w, acc[i][3]);
                acc[i][0] = fmaf(a.w, bb3.x, acc[i][0]); acc[i][1] = fmaf(a.w, bb3.y, acc[i][1]);
                acc[i][2] = fmaf(a.w, bb3.z, acc[i][2]); acc[i][3] = fmaf(a.w, bb3.w, acc[i][3]);
            }
        }
    }
    float4 bias = ((const float4*)b2)[tx];
#pragma unroll
    for (int i = 0; i < 8; i++) {
        int gn = nb + ty * 8 + i;
        if (gn < NN) {
            float4 v = make_float4(acc[i][0] + bias.x, acc[i][1] + bias.y,
                                   acc[i][2] + bias.z, acc[i][3] + bias.w);
            *((float4*)(g_hA + gn * HD + tx * 4)) = v;
        }
    }
}

// ------- layer GEMM: g_hB[n] = (g_hA[n] @ Wg) * dinv[n]  (epilogue-fused) ---
__global__ __launch_bounds__(256) void k_gemm(const float* __restrict__ B)
{
    __shared__ float sA[64][32];
    __shared__ float sB[32][HD];

    int tid = threadIdx.x;
    int tx = tid & 31;
    int ty = tid >> 5;
    int nb = blockIdx.x * 64;

    float acc[8][4];
#pragma unroll
    for (int i = 0; i < 8; i++)
#pragma unroll
        for (int c = 0; c < 4; c++) acc[i][c] = 0.0f;

    for (int kc = 0; kc < 4; kc++) {
        if (kc) __syncthreads();
#pragma unroll
        for (int i = 0; i < 2; i++) {
            int idx = tid + i * 256;
            int r = idx >> 3, c = idx & 7;
            int gn = nb + r;
            float4 v = make_float4(0.f, 0.f, 0.f, 0.f);
            if (gn < NN) v = ((const float4*)(g_hA + gn * HD + kc * 32))[c];
            *((float4*)&sA[r][c * 4]) = v;
        }
        const float4* B4 = (const float4*)(B + kc * 32 * HD);
#pragma unroll
        for (int i = 0; i < 4; i++) ((float4*)sB)[tid + i * 256] = B4[tid + i * 256];
        __syncthreads();
#pragma unroll
        for (int kk = 0; kk < 32; kk += 4) {
            float4 bb0 = *(const float4*)&sB[kk + 0][tx * 4];
            float4 bb1 = *(const float4*)&sB[kk + 1][tx * 4];
            float4 bb2 = *(const float4*)&sB[kk + 2][tx * 4];
            float4 bb3 = *(const float4*)&sB[kk + 3][tx * 4];
#pragma unroll
            for (int i = 0; i < 8; i++) {
                float4 a = *(const float4*)&sA[ty * 8 + i][kk];
                acc[i][0] = fmaf(a.x, bb0.x, acc[i][0]); acc[i][1] = fmaf(a.x, bb0.y, acc[i][1]);
                acc[i][2] = fmaf(a.x, bb0.z, acc[i][2]); acc[i][3] = fmaf(a.x, bb0.w, acc[i][3]);
                acc[i][0] = fmaf(a.y, bb1.x, acc[i][0]); acc[i][1] = fmaf(a.y, bb1.y, acc[i][1]);
                acc[i][2] = fmaf(a.y, bb1.z, acc[i][2]); acc[i][3] = fmaf(a.y, bb1.w, acc[i][3]);
                acc[i][0] = fmaf(a.z, bb2.x, acc[i][0]); acc[i][1] = fmaf(a.z, bb2.y, acc[i][1]);
                acc[i][2] = fmaf(a.z, bb2.z, acc[i][2]); acc[i][3] = fmaf(a.z, bb2.w, acc[i][3]);
                acc[i][0] = fmaf(a.w, bb3.x, acc[i][0]); acc[i][1] = fmaf(a.w, bb3.y, acc[i][1]);
                acc[i][2] = fmaf(a.w, bb3.z, acc[i][2]); acc[i][3] = fmaf(a.w, bb3.w, acc[i][3]);
            }
        }
    }
#pragma unroll
    for (int i = 0; i < 8; i++) {
        int gn = nb + ty * 8 + i;
        if (gn < NN) {
            float d = g_dinv[gn];
            float4 v = make_float4(acc[i][0] * d, acc[i][1] * d, acc[i][2] * d, acc[i][3] * d);
            *((float4*)(g_hB + gn * HD + tx * 4)) = v;
        }
    }
}

// ----- aggregation (CSR gather): g_hA[n] = relu(dinv[n]*(self + Σ src) + bg)
__global__ __launch_bounds__(256) void k_agg(const float* __restrict__ bg) {
    int w = (blockIdx.x * blockDim.x + threadIdx.x) >> 5;
    int lane = threadIdx.x & 31;
    if (w >= NN) return;
    int s = g_rowstart[w];
    int e = s + g_degi[w];

    float4 acc = ((const float4*)g_hB)[w * 32 + lane];   // self term
    int i = s;
    for (; i + 1 < e; i += 2) {
        int s0 = g_csrc[i], s1 = g_csrc[i + 1];
        float4 v0 = ((const float4*)g_hB)[s0 * 32 + lane];
        float4 v1 = ((const float4*)g_hB)[s1 * 32 + lane];
        acc.x += v0.x + v1.x; acc.y += v0.y + v1.y;
        acc.z += v0.z + v1.z; acc.w += v0.w + v1.w;
    }
    if (i < e) {
        float4 v0 = ((const float4*)g_hB)[g_csrc[i] * 32 + lane];
        acc.x += v0.x; acc.y += v0.y; acc.z += v0.z; acc.w += v0.w;
    }
    float d = g_dinv[w];
    float4 bv = ((const float4*)bg)[lane];
    float4 r;
    r.x = fmaxf(fmaf(acc.x, d, bv.x), 0.f);
    r.y = fmaxf(fmaf(acc.y, d, bv.y), 0.f);
    r.z = fmaxf(fmaf(acc.z, d, bv.z), 0.f);
    r.w = fmaxf(fmaf(acc.w, d, bv.w), 0.f);
    ((float4*)g_hA)[w * 32 + lane] = r;
}

// ----- output MLP + readout (tiled GEMM + GEMV + shfl reduce + atomic) ------
// 64 nodes x 64 cols per block; 256 threads; thread = 4 nodes x 4 cols.
__global__ __launch_bounds__(256) void k_final(
    const float* __restrict__ W3, const float* __restrict__ b3,
    const float* __restrict__ W4, const float* __restrict__ b4,
    const int* __restrict__ batch, float* __restrict__ out)
{
    __shared__ float sA[64][32];
    __shared__ float sB[32][64];
    __shared__ float sW4[64];

    int tid = threadIdx.x;
    int tx = tid & 15;       // col group (4 cols of 64)
    int ty = tid >> 4;       // node group (4 nodes of 64)
    int nb = blockIdx.x * 64;

    if (tid < 64) sW4[tid] = W4[tid];

    float acc[4][4];
#pragma unroll
    for (int i = 0; i < 4; i++)
#pragma unroll
        for (int j = 0; j < 4; j++) acc[i][j] = 0.0f;

    for (int kc = 0; kc < 4; kc++) {
        if (kc) __syncthreads();
        // load A tile: 64 nodes x 32 k  (512 float4, 2 per thread)
#pragma unroll
        for (int i = 0; i < 2; i++) {
            int idx = tid + i * 256;
            int r = idx >> 3, c = idx & 7;
            int gn = nb + r;
            float4 v = make_float4(0.f, 0.f, 0.f, 0.f);
            if (gn < NN) v = ((const float4*)(g_hA + gn * HD + kc * 32))[c];
            *((float4*)&sA[r][c * 4]) = v;
        }
        // load B tile: W3 rows kc*32..+31, 64 cols (512 float4, 2 per thread)
        const float4* B4 = (const float4*)(W3 + kc * 32 * 64);
#pragma unroll
        for (int i = 0; i < 2; i++) ((float4*)sB)[tid + i * 256] = B4[tid + i * 256];
        __syncthreads();
#pragma unroll
        for (int kk = 0; kk < 32; kk += 4) {
            float4 bb0 = *(const float4*)&sB[kk + 0][tx * 4];
            float4 bb1 = *(const float4*)&sB[kk + 1][tx * 4];
            float4 bb2 = *(const float4*)&sB[kk + 2][tx * 4];
            float4 bb3 = *(const float4*)&sB[kk + 3][tx * 4];
#pragma unroll
            for (int i = 0; i < 4; i++) {
                float4 a = *(const float4*)&sA[ty * 4 + i][kk];
                acc[i][0] = fmaf(a.x, bb0.x, acc[i][0]); acc[i][1] = fmaf(a.x, bb0.y, acc[i][1]);
                acc[i][2] = fmaf(a.x, bb0.z, acc[i][2]); acc[i][3] = fmaf(a.x, bb0.w, acc[i][3]);
                acc[i][0] = fmaf(a.y, bb1.x, acc[i][0]); acc[i][1] = fmaf(a.y, bb1.y, acc[i][1]);
                acc[i][2] = fmaf(a.y, bb1.z, acc[i][2]); acc[i][3] = fmaf(a.y, bb1.w, acc[i][3]);
                acc[i][0] = fmaf(a.z, bb2.x, acc[i][0]); acc[i][1] = fmaf(a.z, bb2.y, acc[i][1]);
                acc[i][2] = fmaf(a.z, bb2.z, acc[i][2]); acc[i][3] = fmaf(a.z, bb2.w, acc[i][3]);
                acc[i][0] = fmaf(a.w, bb3.x, acc[i][0]); acc[i][1] = fmaf(a.w, bb3.y, acc[i][1]);
                acc[i][2] = fmaf(a.w, bb3.z, acc[i][2]); acc[i][3] = fmaf(a.w, bb3.w, acc[i][3]);
            }
        }
    }

    // stage 2: t = relu(acc + b3), partial[i] = sum_j t[i][j]*W4[col]
    float4 b3v = ((const float4*)b3)[tx];
    float w40 = sW4[tx * 4 + 0], w41 = sW4[tx * 4 + 1];
    float w42 = sW4[tx * 4 + 2], w43 = sW4[tx * 4 + 3];
    float b4v = b4[0];

#pragma unroll
    for (int i = 0; i < 4; i++) {
        float t0 = fmaxf(acc[i][0] + b3v.x, 0.f);
        float t1 = fmaxf(acc[i][1] + b3v.y, 0.f);
        float t2 = fmaxf(acc[i][2] + b3v.z, 0.f);
        float t3 = fmaxf(acc[i][3] + b3v.w, 0.f);
        float p = fmaf(t0, w40, fmaf(t1, w41, fmaf(t2, w42, t3 * w43)));
        // reduce across the 16 tx-threads (contiguous lanes within half-warp)
#pragma unroll
        for (int off = 8; off; off >>= 1) p += __shfl_xor_sync(0xFFFFFFFFu, p, off);
        if (tx == 0) {
            int gn = nb + ty * 4 + i;
            if (gn < NN) atomicAdd(&out[batch[gn]], p + b4v);
        }
    }
}

// ---------------------------------------------------------------------------
extern "C" void kernel_launch(void* const* d_in, const int* in_sizes, int n_in,
                              void* d_out, int out_size)
{
    const float* x     = (const float*)d_in[0];
    const int*   ei    = (const int*)d_in[2];
    const int*   batch = (const int*)d_in[3];
    const float* W1 = (const float*)d_in[4];
    const float* b1 = (const float*)d_in[5];
    const float* W2 = (const float*)d_in[6];
    const float* b2 = (const float*)d_in[7];
    const float* Wg = (const float*)d_in[8];
    const float* bg = (const float*)d_in[9];
    const float* W3 = (const float*)d_in[10];
    const float* b3 = (const float*)d_in[11];
    const float* W4 = (const float*)d_in[12];
    const float* b4 = (const float*)d_in[13];
    float* out = (float*)d_out;

    k_prep<<<(NN + 255) / 256, 256>>>(out);
    k_deg<<<(NE + 255) / 256, 256>>>(ei);
    k_dinv<<<(NN + 255) / 256, 256>>>();
    k_scan1<<<NSCANB, SCAN_B>>>();
    k_scan2<<<1, 32>>>();
    k_scan3<<<(NN + 255) / 256, 256>>>();
    k_fill<<<(NE + 255) / 256, 256>>>(ei);

    k_gemm_in<<<(NN + 63) / 64, 256>>>(x, W1, b1, W2, b2);

    for (int l = 0; l < 3; l++) {
        k_gemm<<<(NN + 63) / 64, 256>>>(Wg + l * HD * HD);
        k_agg<<<(NN * 32 + 255) / 256, 256>>>(bg + l * HD);
    }

    k_final<<<(NN + 63) / 64, 256>>>(W3, b3, W4, b4, batch, out);
}

// round 9
// speedup vs baseline: 1.0068x; 1.0068x over previous
#include <cuda_runtime.h>

#define NN 50000
#define NE 600000
#define HD 128
#define NG 128
#define SCAN_B 1024
#define NSCANB ((NN + SCAN_B - 1) / SCAN_B)   // 49

// ---------------- scratch (static device globals; no allocations) ------------
__device__ float g_hA[NN * HD];     // current node features (relu'd layer output)
__device__ float g_hB[NN * HD];     // m * dinv[row]
__device__ float g_dinv[NN];
__device__ int   g_degi[NN];        // incoming edge count (no self loop)
__device__ int   g_scan[NN];
__device__ int   g_bsum[NSCANB];
__device__ int   g_boff[NSCANB];
__device__ int   g_rowstart[NN];
__device__ int   g_cursor[NN];
__device__ int   g_csrc[NE];        // CSR (by dest): source node ids

// ---------------- f32x2 packed helpers (sm_103a FFMA2 path) -----------------
__device__ __forceinline__ unsigned long long pk2(float v) {
    unsigned long long d;
    asm("mov.b64 %0, {%1, %1};" : "=l"(d) : "f"(v));
    return d;
}
__device__ __forceinline__ void ffma2(unsigned long long& d,
                                      unsigned long long a, unsigned long long b) {
    asm("fma.rn.f32x2 %0, %1, %2, %0;" : "+l"(d) : "l"(a), "l"(b));
}
__device__ __forceinline__ float2 up2(unsigned long long d) {
    float2 f;
    asm("mov.b64 {%0, %1}, %2;" : "=f"(f.x), "=f"(f.y) : "l"(d));
    return f;
}

// ---------------- prep ------------------------------------------------------
__global__ void k_prep(float* __restrict__ out) {
    int i = blockIdx.x * blockDim.x + threadIdx.x;
    if (i < NN) g_degi[i] = 0;
    if (i < NG) out[i] = 0.0f;
}

__global__ void k_deg(const int* __restrict__ ei) {
    int e = blockIdx.x * blockDim.x + threadIdx.x;
    if (e < NE) atomicAdd(&g_degi[ei[NE + e]], 1);
}

__global__ void k_dinv() {
    int i = blockIdx.x * blockDim.x + threadIdx.x;
    if (i < NN) g_dinv[i] = rsqrtf((float)g_degi[i] + 1.0f);
}

// ---------------- scan (exclusive prefix over g_degi) -----------------------
__global__ __launch_bounds__(SCAN_B) void k_scan1() {
    __shared__ int sd[SCAN_B];
    int tid = threadIdx.x;
    int idx = blockIdx.x * SCAN_B + tid;
    int v = (idx < NN) ? g_degi[idx] : 0;
    sd[tid] = v;
    __syncthreads();
    for (int off = 1; off < SCAN_B; off <<= 1) {
        int t = (tid >= off) ? sd[tid - off] : 0;
        __syncthreads();
        sd[tid] += t;
        __syncthreads();
    }
    if (idx < NN) g_scan[idx] = sd[tid];
    if (tid == SCAN_B - 1) g_bsum[blockIdx.x] = sd[tid];
}

__global__ void k_scan2() {
    if (threadIdx.x == 0) {
        int a = 0;
        for (int b = 0; b < NSCANB; b++) { g_boff[b] = a; a += g_bsum[b]; }
    }
}

__global__ void k_scan3() {
    int i = blockIdx.x * blockDim.x + threadIdx.x;
    if (i < NN) {
        int rs = g_scan[i] - g_degi[i] + g_boff[i >> 10];
        g_rowstart[i] = rs;
        g_cursor[i] = rs;
    }
}

__global__ void k_fill(const int* __restrict__ ei) {
    int e = blockIdx.x * blockDim.x + threadIdx.x;
    if (e < NE) {
        int r = ei[e], c = ei[NE + e];
        int slot = atomicAdd(&g_cursor[c], 1);
        g_csrc[slot] = r;
    }
}

// ======================= FFMA2 GEMM mainloop (shared) =======================
// Tile: 64 nodes x 128 cols; 256 threads; thread = 4 nodes x 8 cols.
// tx (0..15): cols tx*4..tx*4+3 and 64+tx*4..64+tx*4+3 (two packed col-pairs each)
// ty (0..15): nodes ty*4..ty*4+3
// acc[i][0..1] = cols tx*4 pairs; acc[i][2..3] = cols 64+tx*4 pairs.
#define GEMM_MAINLOOP(sA_, sB_, acc_, tx_, ty_)                                   \
    _Pragma("unroll")                                                             \
    for (int kk = 0; kk < 32; kk += 4) {                                          \
        float4 a0 = *(const float4*)&sA_[(ty_) * 4 + 0][kk];                      \
        float4 a1 = *(const float4*)&sA_[(ty_) * 4 + 1][kk];                      \
        float4 a2 = *(const float4*)&sA_[(ty_) * 4 + 2][kk];                      \
        float4 a3 = *(const float4*)&sA_[(ty_) * 4 + 3][kk];                      \
        _Pragma("unroll")                                                         \
        for (int j = 0; j < 4; j++) {                                             \
            ulonglong2 bl = *(const ulonglong2*)&sB_[kk + j][(tx_) * 4];          \
            ulonglong2 bh = *(const ulonglong2*)&sB_[kk + j][64 + (tx_) * 4];     \
            float av0 = j == 0 ? a0.x : j == 1 ? a0.y : j == 2 ? a0.z : a0.w;     \
            float av1 = j == 0 ? a1.x : j == 1 ? a1.y : j == 2 ? a1.z : a1.w;     \
            float av2 = j == 0 ? a2.x : j == 1 ? a2.y : j == 2 ? a2.z : a2.w;     \
            float av3 = j == 0 ? a3.x : j == 1 ? a3.y : j == 2 ? a3.z : a3.w;     \
            unsigned long long p0 = pk2(av0), p1 = pk2(av1);                      \
            unsigned long long p2 = pk2(av2), p3 = pk2(av3);                      \
            ffma2(acc_[0][0], p0, bl.x); ffma2(acc_[0][1], p0, bl.y);             \
            ffma2(acc_[0][2], p0, bh.x); ffma2(acc_[0][3], p0, bh.y);             \
            ffma2(acc_[1][0], p1, bl.x); ffma2(acc_[1][1], p1, bl.y);             \
            ffma2(acc_[1][2], p1, bh.x); ffma2(acc_[1][3], p1, bh.y);             \
            ffma2(acc_[2][0], p2, bl.x); ffma2(acc_[2][1], p2, bl.y);             \
            ffma2(acc_[2][2], p2, bh.x); ffma2(acc_[2][3], p2, bh.y);             \
            ffma2(acc_[3][0], p3, bl.x); ffma2(acc_[3][1], p3, bl.y);             \
            ffma2(acc_[3][2], p3, bh.x); ffma2(acc_[3][3], p3, bh.y);             \
        }                                                                         \
    }

// ---------------- input MLP: g_hA = relu(x@W1 + b1) @ W2 + b2 ---------------
__global__ __launch_bounds__(256) void k_gemm_in(
    const float* __restrict__ x,
    const float* __restrict__ W1, const float* __restrict__ b1,
    const float* __restrict__ W2, const float* __restrict__ b2)
{
    __shared__ float sA[64][32];
    __shared__ float sB[32][HD];
    __shared__ float sx[64];
    __shared__ float sW1[32], sb1[32];

    int tid = threadIdx.x;
    int tx = tid & 15;
    int ty = tid >> 4;
    int nb = blockIdx.x * 64;

    if (tid < 64) { int gn = nb + tid; sx[tid] = (gn < NN) ? x[gn] : 0.0f; }

    unsigned long long acc[4][4];
#pragma unroll
    for (int i = 0; i < 4; i++)
#pragma unroll
        for (int c = 0; c < 4; c++) acc[i][c] = 0ull;

    for (int kc = 0; kc < 4; kc++) {
        __syncthreads();
        if (tid < 32) { sW1[tid] = W1[kc * 32 + tid]; sb1[tid] = b1[kc * 32 + tid]; }
        const float4* B4 = (const float4*)(W2 + kc * 32 * HD);
#pragma unroll
        for (int i = 0; i < 4; i++) ((float4*)sB)[tid + i * 256] = B4[tid + i * 256];
        __syncthreads();
#pragma unroll
        for (int i = 0; i < 8; i++) {
            int idx = tid + i * 256;
            int r = idx >> 5, k = idx & 31;
            sA[r][k] = fmaxf(fmaf(sx[r], sW1[k], sb1[k]), 0.0f);
        }
        __syncthreads();
        GEMM_MAINLOOP(sA, sB, acc, tx, ty)
    }

    float4 bl = ((const float4*)b2)[tx];
    float4 bh = ((const float4*)b2)[16 + tx];
#pragma unroll
    for (int i = 0; i < 4; i++) {
        int gn = nb + ty * 4 + i;
        if (gn < NN) {
            float2 v0 = up2(acc[i][0]), v1 = up2(acc[i][1]);
            float2 v2 = up2(acc[i][2]), v3 = up2(acc[i][3]);
            *((float4*)(g_hA + gn * HD + tx * 4)) =
                make_float4(v0.x + bl.x, v0.y + bl.y, v1.x + bl.z, v1.y + bl.w);
            *((float4*)(g_hA + gn * HD + 64 + tx * 4)) =
                make_float4(v2.x + bh.x, v2.y + bh.y, v3.x + bh.z, v3.y + bh.w);
        }
    }
}

// ------- layer GEMM: g_hB[n] = (g_hA[n] @ Wg) * dinv[n]  (epilogue-fused) ---
__global__ __launch_bounds__(256) void k_gemm(const float* __restrict__ B)
{
    __shared__ float sA[64][32];
    __shared__ float sB[32][HD];

    int tid = threadIdx.x;
    int tx = tid & 15;
    int ty = tid >> 4;
    int nb = blockIdx.x * 64;

    unsigned long long acc[4][4];
#pragma unroll
    for (int i = 0; i < 4; i++)
#pragma unroll
        for (int c = 0; c < 4; c++) acc[i][c] = 0ull;

    for (int kc = 0; kc < 4; kc++) {
        if (kc) __syncthreads();
#pragma unroll
        for (int i = 0; i < 2; i++) {
            int idx = tid + i * 256;
            int r = idx >> 3, c = idx & 7;
            int gn = nb + r;
            float4 v = make_float4(0.f, 0.f, 0.f, 0.f);
            if (gn < NN) v = ((const float4*)(g_hA + gn * HD + kc * 32))[c];
            *((float4*)&sA[r][c * 4]) = v;
        }
        const float4* B4 = (const float4*)(B + kc * 32 * HD);
#pragma unroll
        for (int i = 0; i < 4; i++) ((float4*)sB)[tid + i * 256] = B4[tid + i * 256];
        __syncthreads();
        GEMM_MAINLOOP(sA, sB, acc, tx, ty)
    }

#pragma unroll
    for (int i = 0; i < 4; i++) {
        int gn = nb + ty * 4 + i;
        if (gn < NN) {
            float d = g_dinv[gn];
            float2 v0 = up2(acc[i][0]), v1 = up2(acc[i][1]);
            float2 v2 = up2(acc[i][2]), v3 = up2(acc[i][3]);
            *((float4*)(g_hB + gn * HD + tx * 4)) =
                make_float4(v0.x * d, v0.y * d, v1.x * d, v1.y * d);
            *((float4*)(g_hB + gn * HD + 64 + tx * 4)) =
                make_float4(v2.x * d, v2.y * d, v3.x * d, v3.y * d);
        }
    }
}

// ----- aggregation (CSR gather): g_hA[n] = relu(dinv[n]*(self + Σ src) + bg)
__global__ __launch_bounds__(256) void k_agg(const float* __restrict__ bg) {
    int w = (blockIdx.x * blockDim.x + threadIdx.x) >> 5;
    int lane = threadIdx.x & 31;
    if (w >= NN) return;
    int s = g_rowstart[w];
    int e = s + g_degi[w];

    float4 acc = ((const float4*)g_hB)[w * 32 + lane];   // self term
    int i = s;
    for (; i + 1 < e; i += 2) {
        int s0 = g_csrc[i], s1 = g_csrc[i + 1];
        float4 v0 = ((const float4*)g_hB)[s0 * 32 + lane];
        float4 v1 = ((const float4*)g_hB)[s1 * 32 + lane];
        acc.x += v0.x + v1.x; acc.y += v0.y + v1.y;
        acc.z += v0.z + v1.z; acc.w += v0.w + v1.w;
    }
    if (i < e) {
        float4 v0 = ((const float4*)g_hB)[g_csrc[i] * 32 + lane];
        acc.x += v0.x; acc.y += v0.y; acc.z += v0.z; acc.w += v0.w;
    }
    float d = g_dinv[w];
    float4 bv = ((const float4*)bg)[lane];
    float4 r;
    r.x = fmaxf(fmaf(acc.x, d, bv.x), 0.f);
    r.y = fmaxf(fmaf(acc.y, d, bv.y), 0.f);
    r.z = fmaxf(fmaf(acc.z, d, bv.z), 0.f);
    r.w = fmaxf(fmaf(acc.w, d, bv.w), 0.f);
    ((float4*)g_hA)[w * 32 + lane] = r;
}

// ----- output MLP + readout (tiled GEMM + GEMV + shfl reduce + atomic) ------
__global__ __launch_bounds__(256) void k_final(
    const float* __restrict__ W3, const float* __restrict__ b3,
    const float* __restrict__ W4, const float* __restrict__ b4,
    const int* __restrict__ batch, float* __restrict__ out)
{
    __shared__ float sA[64][32];
    __shared__ float sB[32][64];
    __shared__ float sW4[64];

    int tid = threadIdx.x;
    int tx = tid & 15;       // col group (4 cols of 64)
    int ty = tid >> 4;       // node group (4 nodes of 64)
    int nb = blockIdx.x * 64;

    if (tid < 64) sW4[tid] = W4[tid];

    float acc[4][4];
#pragma unroll
    for (int i = 0; i < 4; i++)
#pragma unroll
        for (int j = 0; j < 4; j++) acc[i][j] = 0.0f;

    for (int kc = 0; kc < 4; kc++) {
        if (kc) __syncthreads();
#pragma unroll
        for (int i = 0; i < 2; i++) {
            int idx = tid + i * 256;
            int r = idx >> 3, c = idx & 7;
            int gn = nb + r;
            float4 v = make_float4(0.f, 0.f, 0.f, 0.f);
            if (gn < NN) v = ((const float4*)(g_hA + gn * HD + kc * 32))[c];
            *((float4*)&sA[r][c * 4]) = v;
        }
        const float4* B4 = (const float4*)(W3 + kc * 32 * 64);
#pragma unroll
        for (int i = 0; i < 2; i++) ((float4*)sB)[tid + i * 256] = B4[tid + i * 256];
        __syncthreads();
#pragma unroll
        for (int kk = 0; kk < 32; kk += 4) {
            float4 bb0 = *(const float4*)&sB[kk + 0][tx * 4];
            float4 bb1 = *(const float4*)&sB[kk + 1][tx * 4];
            float4 bb2 = *(const float4*)&sB[kk + 2][tx * 4];
            float4 bb3 = *(const float4*)&sB[kk + 3][tx * 4];
#pragma unroll
            for (int i = 0; i < 4; i++) {
                float4 a = *(const float4*)&sA[ty * 4 + i][kk];
                acc[i][0] = fmaf(a.x, bb0.x, acc[i][0]); acc[i][1] = fmaf(a.x, bb0.y, acc[i][1]);
                acc[i][2] = fmaf(a.x, bb0.z, acc[i][2]); acc[i][3] = fmaf(a.x, bb0.w, acc[i][3]);
                acc[i][0] = fmaf(a.y, bb1.x, acc[i][0]); acc[i][1] = fmaf(a.y, bb1.y, acc[i][1]);
                acc[i][2] = fmaf(a.y, bb1.z, acc[i][2]); acc[i][3] = fmaf(a.y, bb1.w, acc[i][3]);
                acc[i][0] = fmaf(a.z, bb2.x, acc[i][0]); acc[i][1] = fmaf(a.z, bb2.y, acc[i][1]);
                acc[i][2] = fmaf(a.z, bb2.z, acc[i][2]); acc[i][3] = fmaf(a.z, bb2.w, acc[i][3]);
                acc[i][0] = fmaf(a.w, bb3.x, acc[i][0]); acc[i][1] = fmaf(a.w, bb3.y, acc[i][1]);
                acc[i][2] = fmaf(a.w, bb3.z, acc[i][2]); acc[i][3] = fmaf(a.w, bb3.w, acc[i][3]);
            }
        }
    }

    float4 b3v = ((const float4*)b3)[tx];
    float w40 = sW4[tx * 4 + 0], w41 = sW4[tx * 4 + 1];
    float w42 = sW4[tx * 4 + 2], w43 = sW4[tx * 4 + 3];
    float b4v = b4[0];

#pragma unroll
    for (int i = 0; i < 4; i++) {
        float t0 = fmaxf(acc[i][0] + b3v.x, 0.f);
        float t1 = fmaxf(acc[i][1] + b3v.y, 0.f);
        float t2 = fmaxf(acc[i][2] + b3v.z, 0.f);
        float t3 = fmaxf(acc[i][3] + b3v.w, 0.f);
        float p = fmaf(t0, w40, fmaf(t1, w41, fmaf(t2, w42, t3 * w43)));
#pragma unroll
        for (int off = 8; off; off >>= 1) p += __shfl_xor_sync(0xFFFFFFFFu, p, off);
        if (tx == 0) {
            int gn = nb + ty * 4 + i;
            if (gn < NN) atomicAdd(&out[batch[gn]], p + b4v);
        }
    }
}

// ---------------------------------------------------------------------------
extern "C" void kernel_launch(void* const* d_in, const int* in_sizes, int n_in,
                              void* d_out, int out_size)
{
    const float* x     = (const float*)d_in[0];
    const int*   ei    = (const int*)d_in[2];
    const int*   batch = (const int*)d_in[3];
    const float* W1 = (const float*)d_in[4];
    const float* b1 = (const float*)d_in[5];
    const float* W2 = (const float*)d_in[6];
    const float* b2 = (const float*)d_in[7];
    const float* Wg = (const float*)d_in[8];
    const float* bg = (const float*)d_in[9];
    const float* W3 = (const float*)d_in[10];
    const float* b3 = (const float*)d_in[11];
    const float* W4 = (const float*)d_in[12];
    const float* b4 = (const float*)d_in[13];
    float* out = (float*)d_out;

    k_prep<<<(NN + 255) / 256, 256>>>(out);
    k_deg<<<(NE + 255) / 256, 256>>>(ei);
    k_dinv<<<(NN + 255) / 256, 256>>>();
    k_scan1<<<NSCANB, SCAN_B>>>();
    k_scan2<<<1, 32>>>();
    k_scan3<<<(NN + 255) / 256, 256>>>();
    k_fill<<<(NE + 255) / 256, 256>>>(ei);

    k_gemm_in<<<(NN + 63) / 64, 256>>>(x, W1, b1, W2, b2);

    for (int l = 0; l < 3; l++) {
        k_gemm<<<(NN + 63) / 64, 256>>>(Wg + l * HD * HD);
        k_agg<<<(NN * 32 + 255) / 256, 256>>>(bg + l * HD);
    }

    k_final<<<(NN + 63) / 64, 256>>>(W3, b3, W4, b4, batch, out);
}

// round 17
// speedup vs baseline: 1.0764x; 1.0691x over previous
#include <cuda_runtime.h>
#include <cstdint>

#define NN 50000
#define NE 600000
#define HD 128
#define NG 128
#define SCAN_B 1024
#define NSCANB ((NN + SCAN_B - 1) / SCAN_B)   // 49

// ---------------- scratch (static device globals; no allocations) ------------
__device__ float g_hA[NN * HD];     // current node features (relu'd layer output)
__device__ float g_hB[NN * HD];     // m * dinv[row]
__device__ float g_dinv[NN];
__device__ int   g_degi[NN];
__device__ int   g_scan[NN];
__device__ int   g_bsum[NSCANB];
__device__ int   g_boff[NSCANB];
__device__ int   g_rowstart[NN];
__device__ int   g_cursor[NN];
__device__ int   g_csrc[NE];

// ---------------- f32x2 packed helpers (input MLP) --------------------------
__device__ __forceinline__ unsigned long long pk2(float v) {
    unsigned long long d;
    asm("mov.b64 %0, {%1, %1};" : "=l"(d) : "f"(v));
    return d;
}
__device__ __forceinline__ void ffma2(unsigned long long& d,
                                      unsigned long long a, unsigned long long b) {
    asm("fma.rn.f32x2 %0, %1, %2, %0;" : "+l"(d) : "l"(a), "l"(b));
}
__device__ __forceinline__ float2 up2(unsigned long long d) {
    float2 f;
    asm("mov.b64 {%0, %1}, %2;" : "=f"(f.x), "=f"(f.y) : "l"(d));
    return f;
}

// ---------------- tf32 helpers ----------------------------------------------
__device__ __forceinline__ float tf32r(float x) {
    float y;
    asm("cvt.rna.tf32.f32 %0, %1;" : "=f"(y) : "f"(x));
    return y;
}
__device__ __forceinline__ void tsplit(float x, uint32_t& hi, uint32_t& lo) {
    float h = tf32r(x);
    float l = tf32r(x - h);
    hi = __float_as_uint(h);
    lo = __float_as_uint(l);
}

// m16n8k8 tf32 MMA, row.col, f32 accum
#define MMA8(c, a, b)                                                              \
    asm volatile("mma.sync.aligned.m16n8k8.row.col.f32.tf32.tf32.f32 "             \
        "{%0,%1,%2,%3},{%4,%5,%6,%7},{%8,%9},{%0,%1,%2,%3};"                       \
        : "+f"((c)[0]), "+f"((c)[1]), "+f"((c)[2]), "+f"((c)[3])                    \
        : "r"((a)[0]), "r"((a)[1]), "r"((a)[2]), "r"((a)[3]),                       \
          "r"((b)[0]), "r"((b)[1]))

// ---------------- prep ------------------------------------------------------
__global__ void k_prep(float* __restrict__ out) {
    int i = blockIdx.x * blockDim.x + threadIdx.x;
    if (i < NN) g_degi[i] = 0;
    if (i < NG) out[i] = 0.0f;
}

__global__ void k_deg(const int* __restrict__ ei) {
    int e = blockIdx.x * blockDim.x + threadIdx.x;
    if (e < NE) atomicAdd(&g_degi[ei[NE + e]], 1);
}

__global__ void k_dinv() {
    int i = blockIdx.x * blockDim.x + threadIdx.x;
    if (i < NN) g_dinv[i] = rsqrtf((float)g_degi[i] + 1.0f);
}

// ---------------- scan (exclusive prefix over g_degi) -----------------------
__global__ __launch_bounds__(SCAN_B) void k_scan1() {
    __shared__ int sd[SCAN_B];
    int tid = threadIdx.x;
    int idx = blockIdx.x * SCAN_B + tid;
    int v = (idx < NN) ? g_degi[idx] : 0;
    sd[tid] = v;
    __syncthreads();
    for (int off = 1; off < SCAN_B; off <<= 1) {
        int t = (tid >= off) ? sd[tid - off] : 0;
        __syncthreads();
        sd[tid] += t;
        __syncthreads();
    }
    if (idx < NN) g_scan[idx] = sd[tid];
    if (tid == SCAN_B - 1) g_bsum[blockIdx.x] = sd[tid];
}

__global__ void k_scan2() {
    if (threadIdx.x == 0) {
        int a = 0;
        for (int b = 0; b < NSCANB; b++) { g_boff[b] = a; a += g_bsum[b]; }
    }
}

__global__ void k_scan3() {
    int i = blockIdx.x * blockDim.x + threadIdx.x;
    if (i < NN) {
        int rs = g_scan[i] - g_degi[i] + g_boff[i >> 10];
        g_rowstart[i] = rs;
        g_cursor[i] = rs;
    }
}

__global__ void k_fill(const int* __restrict__ ei) {
    int e = blockIdx.x * blockDim.x + threadIdx.x;
    if (e < NE) {
        int r = ei[e], c = ei[NE + e];
        int slot = atomicAdd(&g_cursor[c], 1);
        g_csrc[slot] = r;
    }
}

// ======================= FFMA2 GEMM mainloop (input MLP) =====================
#define GEMM_MAINLOOP(sA_, sB_, acc_, tx_, ty_)                                   \
    _Pragma("unroll")                                                             \
    for (int kk = 0; kk < 32; kk += 4) {                                          \
        float4 a0 = *(const float4*)&sA_[(ty_) * 4 + 0][kk];                      \
        float4 a1 = *(const float4*)&sA_[(ty_) * 4 + 1][kk];                      \
        float4 a2 = *(const float4*)&sA_[(ty_) * 4 + 2][kk];                      \
        float4 a3 = *(const float4*)&sA_[(ty_) * 4 + 3][kk];                      \
        _Pragma("unroll")                                                         \
        for (int j = 0; j < 4; j++) {                                             \
            ulonglong2 bl = *(const ulonglong2*)&sB_[kk + j][(tx_) * 4];          \
            ulonglong2 bh = *(const ulonglong2*)&sB_[kk + j][64 + (tx_) * 4];     \
            float av0 = j == 0 ? a0.x : j == 1 ? a0.y : j == 2 ? a0.z : a0.w;     \
            float av1 = j == 0 ? a1.x : j == 1 ? a1.y : j == 2 ? a1.z : a1.w;     \
            float av2 = j == 0 ? a2.x : j == 1 ? a2.y : j == 2 ? a2.z : a2.w;     \
            float av3 = j == 0 ? a3.x : j == 1 ? a3.y : j == 2 ? a3.z : a3.w;     \
            unsigned long long p0 = pk2(av0), p1 = pk2(av1);                      \
            unsigned long long p2 = pk2(av2), p3 = pk2(av3);                      \
            ffma2(acc_[0][0], p0, bl.x); ffma2(acc_[0][1], p0, bl.y);             \
            ffma2(acc_[0][2], p0, bh.x); ffma2(acc_[0][3], p0, bh.y);             \
            ffma2(acc_[1][0], p1, bl.x); ffma2(acc_[1][1], p1, bl.y);             \
            ffma2(acc_[1][2], p1, bh.x); ffma2(acc_[1][3], p1, bh.y);             \
            ffma2(acc_[2][0], p2, bl.x); ffma2(acc_[2][1], p2, bl.y);             \
            ffma2(acc_[2][2], p2, bh.x); ffma2(acc_[2][3], p2, bh.y);             \
            ffma2(acc_[3][0], p3, bl.x); ffma2(acc_[3][1], p3, bl.y);             \
            ffma2(acc_[3][2], p3, bh.x); ffma2(acc_[3][3], p3, bh.y);             \
        }                                                                         \
    }

// ---------------- input MLP: g_hA = relu(x@W1 + b1) @ W2 + b2 ---------------
__global__ __launch_bounds__(256) void k_gemm_in(
    const float* __restrict__ x,
    const float* __restrict__ W1, const float* __restrict__ b1,
    const float* __restrict__ W2, const float* __restrict__ b2)
{
    __shared__ float sA[64][32];
    __shared__ float sB[32][HD];
    __shared__ float sx[64];
    __shared__ float sW1[32], sb1[32];

    int tid = threadIdx.x;
    int tx = tid & 15;
    int ty = tid >> 4;
    int nb = blockIdx.x * 64;

    if (tid < 64) { int gn = nb + tid; sx[tid] = (gn < NN) ? x[gn] : 0.0f; }

    unsigned long long acc[4][4];
#pragma unroll
    for (int i = 0; i < 4; i++)
#pragma unroll
        for (int c = 0; c < 4; c++) acc[i][c] = 0ull;

    for (int kc = 0; kc < 4; kc++) {
        __syncthreads();
        if (tid < 32) { sW1[tid] = W1[kc * 32 + tid]; sb1[tid] = b1[kc * 32 + tid]; }
        const float4* B4 = (const float4*)(W2 + kc * 32 * HD);
#pragma unroll
        for (int i = 0; i < 4; i++) ((float4*)sB)[tid + i * 256] = B4[tid + i * 256];
        __syncthreads();
#pragma unroll
        for (int i = 0; i < 8; i++) {
            int idx = tid + i * 256;
            int r = idx >> 5, k = idx & 31;
            sA[r][k] = fmaxf(fmaf(sx[r], sW1[k], sb1[k]), 0.0f);
        }
        __syncthreads();
        GEMM_MAINLOOP(sA, sB, acc, tx, ty)
    }

    float4 bl = ((const float4*)b2)[tx];
    float4 bh = ((const float4*)b2)[16 + tx];
#pragma unroll
    for (int i = 0; i < 4; i++) {
        int gn = nb + ty * 4 + i;
        if (gn < NN) {
            float2 v0 = up2(acc[i][0]), v1 = up2(acc[i][1]);
            float2 v2 = up2(acc[i][2]), v3 = up2(acc[i][3]);
            *((float4*)(g_hA + gn * HD + tx * 4)) =
                make_float4(v0.x + bl.x, v0.y + bl.y, v1.x + bl.z, v1.y + bl.w);
            *((float4*)(g_hA + gn * HD + 64 + tx * 4)) =
                make_float4(v2.x + bh.x, v2.y + bh.y, v3.x + bh.z, v3.y + bh.w);
        }
    }
}

// ===== tf32 mma.sync layer GEMM (3xTF32): g_hB[n] = (g_hA[n]@Wg[l])*dinv[n] ==
// CTA: 128 nodes x 128 cols, 8 warps as 4(M) x 2(N); warp tile 32x64.
__global__ __launch_bounds__(256) void k_gemmT(const float* __restrict__ B)
{
    __shared__ float sA[128][36];   // 32-k chunk of A, pad 4 (conflict-free frags)
    __shared__ float sB[32][136];   // 32-k chunk of B [k][n], pad 8

    int tid = threadIdx.x;
    int wid = tid >> 5, lane = tid & 31;
    int g = lane >> 2, t = lane & 3;
    int wm = wid & 3;               // M-warp: rows wm*32..+31
    int wn = wid >> 2;              // N-warp: cols wn*64..+63
    int nb = blockIdx.x * 128;

    float c[2][8][4];
#pragma unroll
    for (int mi = 0; mi < 2; mi++)
#pragma unroll
        for (int ni = 0; ni < 8; ni++)
#pragma unroll
            for (int j = 0; j < 4; j++) c[mi][ni][j] = 0.0f;

    for (int kc = 0; kc < 4; kc++) {
        if (kc) __syncthreads();
        // stage A chunk: 128 rows x 32 k (1024 float4)
#pragma unroll
        for (int i = 0; i < 4; i++) {
            int idx = tid + i * 256;
            int row = idx >> 3, c4 = idx & 7;
            int gn = nb + row;
            float4 v = make_float4(0.f, 0.f, 0.f, 0.f);
            if (gn < NN) v = *(const float4*)(g_hA + gn * HD + kc * 32 + c4 * 4);
            *(float4*)&sA[row][c4 * 4] = v;
        }
        // stage B chunk: Wg rows kc*32..+31, all 128 cols (1024 float4)
#pragma unroll
        for (int i = 0; i < 4; i++) {
            int idx = tid + i * 256;
            int row = idx >> 5, c4 = idx & 31;
            float4 v = *(const float4*)(B + (kc * 32 + row) * HD + c4 * 4);
            *(float4*)&sB[row][c4 * 4] = v;
        }
        __syncthreads();

#pragma unroll
        for (int ks = 0; ks < 4; ks++) {
            // A fragments (hi/lo split)
            uint32_t Ah[2][4], Al[2][4];
#pragma unroll
            for (int mi = 0; mi < 2; mi++) {
                const float* pa = &sA[wm * 32 + mi * 16 + g][ks * 8 + t];
                tsplit(pa[0],          Ah[mi][0], Al[mi][0]);
                tsplit(pa[8 * 36],     Ah[mi][1], Al[mi][1]);
                tsplit(pa[4],          Ah[mi][2], Al[mi][2]);
                tsplit(pa[8 * 36 + 4], Ah[mi][3], Al[mi][3]);
            }
            // B fragments (hi/lo split)
            uint32_t Bh[8][2], Bl[8][2];
#pragma unroll
            for (int ni = 0; ni < 8; ni++) {
                const float* pb = &sB[ks * 8 + t][wn * 64 + ni * 8 + g];
                tsplit(pb[0],       Bh[ni][0], Bl[ni][0]);
                tsplit(pb[4 * 136], Bh[ni][1], Bl[ni][1]);
            }
            // 3xTF32: hi*hi + hi*lo + lo*hi
#pragma unroll
            for (int mi = 0; mi < 2; mi++)
#pragma unroll
                for (int ni = 0; ni < 8; ni++) {
                    MMA8(c[mi][ni], Ah[mi], Bl[ni]);
                    MMA8(c[mi][ni], Al[mi], Bh[ni]);
                    MMA8(c[mi][ni], Ah[mi], Bh[ni]);
                }
        }
    }

    // epilogue: scale by dinv, store
#pragma unroll
    for (int mi = 0; mi < 2; mi++) {
        int r0 = nb + wm * 32 + mi * 16 + g;
        int r1 = r0 + 8;
        float d0 = (r0 < NN) ? g_dinv[r0] : 0.0f;
        float d1 = (r1 < NN) ? g_dinv[r1] : 0.0f;
#pragma unroll
        for (int ni = 0; ni < 8; ni++) {
            int col = wn * 64 + ni * 8 + 2 * t;
            if (r0 < NN)
                *(float2*)(g_hB + r0 * HD + col) =
                    make_float2(c[mi][ni][0] * d0, c[mi][ni][1] * d0);
            if (r1 < NN)
                *(float2*)(g_hB + r1 * HD + col) =
                    make_float2(c[mi][ni][2] * d1, c[mi][ni][3] * d1);
        }
    }
}

// ----- aggregation (CSR gather): g_hA[n] = relu(dinv[n]*(self + Σ src) + bg)
__global__ __launch_bounds__(256) void k_agg(const float* __restrict__ bg) {
    int w = (blockIdx.x * blockDim.x + threadIdx.x) >> 5;
    int lane = threadIdx.x & 31;
    if (w >= NN) return;
    int s = g_rowstart[w];
    int e = s + g_degi[w];

    float4 acc = ((const float4*)g_hB)[w * 32 + lane];   // self term
    int i = s;
    for (; i + 1 < e; i += 2) {
        int s0 = g_csrc[i], s1 = g_csrc[i + 1];
        float4 v0 = ((const float4*)g_hB)[s0 * 32 + lane];
        float4 v1 = ((const float4*)g_hB)[s1 * 32 + lane];
        acc.x += v0.x + v1.x; acc.y += v0.y + v1.y;
        acc.z += v0.z + v1.z; acc.w += v0.w + v1.w;
    }
    if (i < e) {
        float4 v0 = ((const float4*)g_hB)[g_csrc[i] * 32 + lane];
        acc.x += v0.x; acc.y += v0.y; acc.z += v0.z; acc.w += v0.w;
    }
    float d = g_dinv[w];
    float4 bv = ((const float4*)bg)[lane];
    float4 r;
    r.x = fmaxf(fmaf(acc.x, d, bv.x), 0.f);
    r.y = fmaxf(fmaf(acc.y, d, bv.y), 0.f);
    r.z = fmaxf(fmaf(acc.z, d, bv.z), 0.f);
    r.w = fmaxf(fmaf(acc.w, d, bv.w), 0.f);
    ((float4*)g_hA)[w * 32 + lane] = r;
}

// ----- output MLP + readout (tiled GEMM + GEMV + shfl reduce + atomic) ------
__global__ __launch_bounds__(256) void k_final(
    const float* __restrict__ W3, const float* __restrict__ b3,
    const float* __restrict__ W4, const float* __restrict__ b4,
    const int* __restrict__ batch, float* __restrict__ out)
{
    __shared__ float sA[64][32];
    __shared__ float sB[32][64];
    __shared__ float sW4[64];

    int tid = threadIdx.x;
    int tx = tid & 15;
    int ty = tid >> 4;
    int nb = blockIdx.x * 64;

    if (tid < 64) sW4[tid] = W4[tid];

    float acc[4][4];
#pragma unroll
    for (int i = 0; i < 4; i++)
#pragma unroll
        for (int j = 0; j < 4; j++) acc[i][j] = 0.0f;

    for (int kc = 0; kc < 4; kc++) {
        if (kc) __syncthreads();
#pragma unroll
        for (int i = 0; i < 2; i++) {
            int idx = tid + i * 256;
            int r = idx >> 3, c = idx & 7;
            int gn = nb + r;
            float4 v = make_float4(0.f, 0.f, 0.f, 0.f);
            if (gn < NN) v = ((const float4*)(g_hA + gn * HD + kc * 32))[c];
            *((float4*)&sA[r][c * 4]) = v;
        }
        const float4* B4 = (const float4*)(W3 + kc * 32 * 64);
#pragma unroll
        for (int i = 0; i < 2; i++) ((float4*)sB)[tid + i * 256] = B4[tid + i * 256];
        __syncthreads();
#pragma unroll
        for (int kk = 0; kk < 32; kk += 4) {
            float4 bb0 = *(const float4*)&sB[kk + 0][tx * 4];
            float4 bb1 = *(const float4*)&sB[kk + 1][tx * 4];
            float4 bb2 = *(const float4*)&sB[kk + 2][tx * 4];
            float4 bb3 = *(const float4*)&sB[kk + 3][tx * 4];
#pragma unroll
            for (int i = 0; i < 4; i++) {
                float4 a = *(const float4*)&sA[ty * 4 + i][kk];
                acc[i][0] = fmaf(a.x, bb0.x, acc[i][0]); acc[i][1] = fmaf(a.x, bb0.y, acc[i][1]);
                acc[i][2] = fmaf(a.x, bb0.z, acc[i][2]); acc[i][3] = fmaf(a.x, bb0.w, acc[i][3]);
                acc[i][0] = fmaf(a.y, bb1.x, acc[i][0]); acc[i][1] = fmaf(a.y, bb1.y, acc[i][1]);
                acc[i][2] = fmaf(a.y, bb1.z, acc[i][2]); acc[i][3] = fmaf(a.y, bb1.w, acc[i][3]);
                acc[i][0] = fmaf(a.z, bb2.x, acc[i][0]); acc[i][1] = fmaf(a.z, bb2.y, acc[i][1]);
                acc[i][2] = fmaf(a.z, bb2.z, acc[i][2]); acc[i][3] = fmaf(a.z, bb2.w, acc[i][3]);
                acc[i][0] = fmaf(a.w, bb3.x, acc[i][0]); acc[i][1] = fmaf(a.w, bb3.y, acc[i][1]);
                acc[i][2] = fmaf(a.w, bb3.z, acc[i][2]); acc[i][3] = fmaf(a.w, bb3.w, acc[i][3]);
            }
        }
    }

    float4 b3v = ((const float4*)b3)[tx];
    float w40 = sW4[tx * 4 + 0], w41 = sW4[tx * 4 + 1];
    float w42 = sW4[tx * 4 + 2], w43 = sW4[tx * 4 + 3];
    float b4v = b4[0];

#pragma unroll
    for (int i = 0; i < 4; i++) {
        float t0 = fmaxf(acc[i][0] + b3v.x, 0.f);
        float t1 = fmaxf(acc[i][1] + b3v.y, 0.f);
        float t2 = fmaxf(acc[i][2] + b3v.z, 0.f);
        float t3 = fmaxf(acc[i][3] + b3v.w, 0.f);
        float p = fmaf(t0, w40, fmaf(t1, w41, fmaf(t2, w42, t3 * w43)));
#pragma unroll
        for (int off = 8; off; off >>= 1) p += __shfl_xor_sync(0xFFFFFFFFu, p, off);
        if (tx == 0) {
            int gn = nb + ty * 4 + i;
            if (gn < NN) atomicAdd(&out[batch[gn]], p + b4v);
        }
    }
}

// ---------------------------------------------------------------------------
extern "C" void kernel_launch(void* const* d_in, const int* in_sizes, int n_in,
                              void* d_out, int out_size)
{
    const float* x     = (const float*)d_in[0];
    const int*   ei    = (const int*)d_in[2];
    const int*   batch = (const int*)d_in[3];
    const float* W1 = (const float*)d_in[4];
    const float* b1 = (const float*)d_in[5];
    const float* W2 = (const float*)d_in[6];
    const float* b2 = (const float*)d_in[7];
    const float* Wg = (const float*)d_in[8];
    const float* bg = (const float*)d_in[9];
    const float* W3 = (const float*)d_in[10];
    const float* b3 = (const float*)d_in[11];
    const float* W4 = (const float*)d_in[12];
    const float* b4 = (const float*)d_in[13];
    float* out = (float*)d_out;

    k_prep<<<(NN + 255) / 256, 256>>>(out);
    k_deg<<<(NE + 255) / 256, 256>>>(ei);
    k_dinv<<<(NN + 255) / 256, 256>>>();
    k_scan1<<<NSCANB, SCAN_B>>>();
    k_scan2<<<1, 32>>>();
    k_scan3<<<(NN + 255) / 256, 256>>>();
    k_fill<<<(NE + 255) / 256, 256>>>(ei);

    k_gemm_in<<<(NN + 63) / 64, 256>>>(x, W1, b1, W2, b2);

    for (int l = 0; l < 3; l++) {
        k_gemmT<<<(NN + 127) / 128, 256>>>(Wg + l * HD * HD);
        k_agg<<<(NN * 32 + 255) / 256, 256>>>(bg + l * HD);
    }

    k_final<<<(NN + 63) / 64, 256>>>(W3, b3, W4, b4, batch, out);
}